// round 15
// baseline (speedup 1.0000x reference)
#include <cuda_runtime.h>
#include <cuda_fp16.h>
#include <cstdint>

// Problem constants
#define BB   16
#define CC   256
#define HH   64
#define WW   64
#define KK   4
#define OO   256
#define HID  65
#define TEMP 34.0f
#define C2   128                        // channel pairs

// Conv tiling: CTA 128(o) x 256(px), 512 thr = 16 warps of 64x32.
// K chunk = 32 ch = 2 x k16 MMA steps.  fp16 data, fp32 accumulate.
#define AST2  24                        // A smem row stride (half2 units, 96 B)
#define SA_SZ (128 * AST2 * 4)          // 12288 B per A stage
#define BROW2 72                        // B row stride (half2)
#define BCH2  440                       // B c2-row stride (half2) = 6*72+8
#define SB_SZ (16 * BCH2 * 4)           // 28160 B per B stage (16 c2-rows)
#define SB_OFF (4 * SA_SZ)              // 49152
#define SMEM_TOTAL (SB_OFF + 2 * SB_SZ) // 105472 (103 KB)

// Scratch
__device__ float  g_pooled[BB * CC];
__device__ float  g_att[BB * KK];
__device__ float  g_aggb[BB * OO];
__device__ __half2 g_wh[(size_t)BB * 9 * OO * C2];       // [b][tap][o][c2'], perm, fp16
__device__ __half2 g_xh[(size_t)BB * C2 * HH * WW];      // [b][c2][p], (even,odd) ch

__device__ __forceinline__ uint32_t smem_u32(const void* p) {
    uint32_t a;
    asm("{ .reg .u64 t; cvta.to.shared.u64 t, %1; cvt.u32.u64 %0, t; }" : "=r"(a) : "l"(p));
    return a;
}
#define CP16(dst, src) \
    asm volatile("cp.async.cg.shared.global [%0], [%1], 16;" :: "r"(dst), "l"(src) : "memory")
#define CP16Z(dst, src, sz) \
    asm volatile("cp.async.cg.shared.global [%0], [%1], 16, %2;" :: "r"(dst), "l"(src), "r"(sz) : "memory")
#define CP_COMMIT() asm volatile("cp.async.commit_group;" ::: "memory")
#define CP_WAIT1()  asm volatile("cp.async.wait_group 1;" ::: "memory")

// ---------------------------------------------------------------------------
// K1: global average pool (fp32) + fp16 channel-pair-interleaved copy of x.
// ---------------------------------------------------------------------------
__global__ void pool_kernel(const float* __restrict__ x) {
    int blk = blockIdx.x;
    int b = blk >> 7, c2 = blk & 127;
    const float4* p0 = reinterpret_cast<const float4*>(x + ((size_t)(b * CC + 2 * c2)) * (HH * WW));
    const float4* p1 = reinterpret_cast<const float4*>(x + ((size_t)(b * CC + 2 * c2 + 1)) * (HH * WW));
    uint4* xo = reinterpret_cast<uint4*>(g_xh + ((size_t)(b * C2 + c2)) * (HH * WW));
    float sa = 0.f, sb = 0.f;
    for (int i = threadIdx.x; i < HH * WW / 4; i += blockDim.x) {
        float4 va = p0[i], vb = p1[i];
        sa += (va.x + va.y) + (va.z + va.w);
        sb += (vb.x + vb.y) + (vb.z + vb.w);
        __half2 h0 = __halves2half2(__float2half_rn(va.x), __float2half_rn(vb.x));
        __half2 h1 = __halves2half2(__float2half_rn(va.y), __float2half_rn(vb.y));
        __half2 h2 = __halves2half2(__float2half_rn(va.z), __float2half_rn(vb.z));
        __half2 h3 = __halves2half2(__float2half_rn(va.w), __float2half_rn(vb.w));
        uint4 o;
        o.x = *(uint32_t*)&h0; o.y = *(uint32_t*)&h1;
        o.z = *(uint32_t*)&h2; o.w = *(uint32_t*)&h3;
        xo[i] = o;
    }
    #pragma unroll
    for (int off = 16; off > 0; off >>= 1) {
        sa += __shfl_down_sync(0xffffffffu, sa, off);
        sb += __shfl_down_sync(0xffffffffu, sb, off);
    }
    __shared__ float wsa[8], wsb[8];
    int lane = threadIdx.x & 31, wid = threadIdx.x >> 5;
    if (lane == 0) { wsa[wid] = sa; wsb[wid] = sb; }
    __syncthreads();
    if (threadIdx.x == 0) {
        float ta = 0.f, tb = 0.f;
        int nw = blockDim.x >> 5;
        for (int i = 0; i < nw; i++) { ta += wsa[i]; tb += wsb[i]; }
        g_pooled[b * CC + 2 * c2]     = ta * (1.0f / (HH * WW));
        g_pooled[b * CC + 2 * c2 + 1] = tb * (1.0f / (HH * WW));
    }
}

// ---------------------------------------------------------------------------
// K2: attention MLP + softmax + aggregated bias
// ---------------------------------------------------------------------------
__global__ void att_kernel(const float* __restrict__ w_fc1,
                           const float* __restrict__ w_fc2,
                           const float* __restrict__ b_fc2,
                           const float* __restrict__ bias) {
    int b = blockIdx.x;
    __shared__ float sp[CC];
    __shared__ float sh[HID];
    __shared__ float satt[KK];
    for (int i = threadIdx.x; i < CC; i += blockDim.x) sp[i] = g_pooled[b * CC + i];
    __syncthreads();
    if (threadIdx.x < HID) {
        float a = 0.f;
        const float* wr = w_fc1 + threadIdx.x * CC;
        for (int j = 0; j < CC; j++) a += sp[j] * wr[j];
        sh[threadIdx.x] = fmaxf(a, 0.f);
    }
    __syncthreads();
    if (threadIdx.x == 0) {
        float lg[KK];
        float m = -1e30f;
        for (int k = 0; k < KK; k++) {
            float a = b_fc2[k];
            for (int j = 0; j < HID; j++) a += sh[j] * w_fc2[k * HID + j];
            a *= (1.0f / TEMP);
            lg[k] = a;
            m = fmaxf(m, a);
        }
        float den = 0.f;
        for (int k = 0; k < KK; k++) { lg[k] = expf(lg[k] - m); den += lg[k]; }
        float inv = 1.0f / den;
        for (int k = 0; k < KK; k++) satt[k] = lg[k] * inv;
    }
    __syncthreads();
    if (threadIdx.x < KK) g_att[b * KK + threadIdx.x] = satt[threadIdx.x];
    for (int o = threadIdx.x; o < OO; o += blockDim.x) {
        float a = 0.f;
        #pragma unroll
        for (int k = 0; k < KK; k++) a += satt[k] * bias[k * OO + o];
        g_aggb[b * OO + o] = a;
    }
}

// ---------------------------------------------------------------------------
// K3: aggregate weights -> g_wh[b][tap][o][c2'] (fp16 half2, perm within
// 8-half2 k16-blocks: j<4 -> 2j, j>=4 -> 2(j-4)+1).  weight read ONCE.
// ---------------------------------------------------------------------------
__global__ void aggw_kernel(const float* __restrict__ weight) {
    int o = blockIdx.x;
    int c2 = threadIdx.x;              // 0..127
    __shared__ float satt[BB * KK];
    if (c2 < BB * KK) satt[c2] = g_att[c2];
    __syncthreads();
    float wv0[KK][9], wv1[KK][9];
    #pragma unroll
    for (int k = 0; k < KK; k++) {
        const float* wp = weight + (((size_t)k * OO + o) * CC + 2 * c2) * 9;
        #pragma unroll
        for (int t = 0; t < 9; t++) { wv0[k][t] = wp[t]; wv1[k][t] = wp[9 + t]; }
    }
    int j = c2 & 7;
    int cpos = (c2 & ~7) | ((j < 4) ? (2 * j) : (2 * (j - 4) + 1));
    for (int b = 0; b < BB; b++) {
        float a0 = satt[b * KK + 0], a1 = satt[b * KK + 1];
        float a2 = satt[b * KK + 2], a3 = satt[b * KK + 3];
        #pragma unroll
        for (int t = 0; t < 9; t++) {
            float v0 = a0 * wv0[0][t] + a1 * wv0[1][t] + a2 * wv0[2][t] + a3 * wv0[3][t];
            float v1 = a0 * wv1[0][t] + a1 * wv1[1][t] + a2 * wv1[2][t] + a3 * wv1[3][t];
            g_wh[(((size_t)b * 9 + t) * OO + o) * C2 + cpos] =
                __halves2half2(__float2half_rn(v0), __float2half_rn(v1));
        }
    }
}

// ---------------------------------------------------------------------------
// K4: fp16 m16n8k16 mma.sync implicit-GEMM conv, register-pipelined mainloop.
// 512 thr = 16 warps (2 o-halves x 8 px-groups).  Warp tile 64x32.
// Next-chunk ks0 fragments prefetched into regs during current ks1 MMAs, so
// post-barrier MMAs issue immediately (no LDS burst exposure).
// ---------------------------------------------------------------------------
__global__ void __launch_bounds__(512, 1)
conv_mma_kernel(float* __restrict__ out) {
    extern __shared__ char smem[];
    __half2* smh = (__half2*)smem;
    const uint32_t sbu = smem_u32(smem);
    const int tid  = threadIdx.x;
    const int lane = tid & 31;
    const int w    = tid >> 5;
    const int wo   = w >> 3;
    const int wp   = w & 7;
    const int pr   = wp >> 1;
    const int ph   = wp & 1;
    const int gid  = lane >> 2;
    const int kq   = lane & 3;
    const int b  = blockIdx.x;
    const int o0 = blockIdx.y * 128;
    const int r0 = blockIdx.z * 4;

    const __half2* xb = g_xh + (size_t)b * C2 * HH * WW;
    const __half2* wb = g_wh + (size_t)b * 9 * OO * C2;

    // zero halo half2 cells (pos 3 = x col -1, pos 68 = x col 64), both B stages
    for (int i = tid; i < 2 * 16 * 6 * 2; i += 512) {
        int st  = i / 192;
        int rem = i - st * 192;
        int c = rem / 12, r2 = rem - c * 12;
        int rr = r2 >> 1, h = r2 & 1;
        smh[(SB_OFF / 4) + st * (SB_SZ / 4) + c * BCH2 + rr * BROW2 + (h ? 68 : 3)] =
            __halves2half2(__float2half_rn(0.f), __float2half_rn(0.f));
    }

    float acc[4][4][4];
    #pragma unroll
    for (int mi = 0; mi < 4; mi++)
        #pragma unroll
        for (int ni = 0; ni < 4; ni++)
            #pragma unroll
            for (int q = 0; q < 4; q++) acc[mi][ni][q] = 0.f;

    // ---- staging helpers
    auto stageA = [&](int ch) {
        int cg = ch / 9, tap = ch - cg * 9;
        uint32_t dst0 = sbu + (uint32_t)((ch & 3) * SA_SZ);
        const __half2* src0 = wb + ((size_t)tap * OO + o0) * C2 + cg * 16;
        int row = tid >> 2, seg = tid & 3;
        CP16(dst0 + (uint32_t)((row * AST2 + seg * 4) * 4),
             src0 + (size_t)row * C2 + seg * 4);
    };
    auto stageBslice = [&](int cg, int k) {
        int j = tid + k * 512;
        int c = j / 96, rem = j - c * 96;
        int row = rem >> 4, seg = rem & 15;
        int rr = r0 - 1 + row;
        bool ok = (unsigned)rr < (unsigned)HH;
        const __half2* src = xb + ((size_t)(cg * 16 + c) * HH + (ok ? rr : 0)) * WW + seg * 4;
        uint32_t dst = sbu + SB_OFF + (uint32_t)((cg & 1) * SB_SZ)
                     + (uint32_t)((c * BCH2 + row * BROW2 + 4 + seg * 4) * 4);
        CP16Z(dst, src, ok ? 16 : 0);
    };

    // ---- fragment helpers
    auto aptr = [&](int ch) -> const __half2* {
        return smh + (ch & 3) * (SA_SZ / 4) + (wo * 64 + gid) * AST2;
    };
    auto bptr = [&](int ch) -> const __half2* {
        int cg = ch / 9, tap = ch - cg * 9;
        int dy = tap / 3 - 1, dx = tap - (tap / 3) * 3 - 1;
        return smh + (SB_OFF / 4) + (cg & 1) * (SB_SZ / 4)
             + (1 + pr + dy) * BROW2 + 4 + ph * 32 + gid + dx;
    };
    auto loadA = [&](const __half2* A, int ks, uint2* lo, uint2* hi) {
        #pragma unroll
        for (int mi = 0; mi < 4; mi++) {
            const __half2* p = A + mi * 16 * AST2 + ks * 8 + kq * 2;
            lo[mi] = *(const uint2*)p;
            hi[mi] = *(const uint2*)(p + 8 * AST2);
        }
    };
    auto loadB = [&](const __half2* Bc, int ks, uint32_t (*bf)[2]) {
        const __half2* Bk = Bc + (8 * ks + kq) * BCH2;
        #pragma unroll
        for (int ni = 0; ni < 4; ni++) {
            bf[ni][0] = *(const uint32_t*)(Bk + ni * 8);
            bf[ni][1] = *(const uint32_t*)(Bk + 4 * BCH2 + ni * 8);
        }
    };
    auto mmas = [&](const uint2* lo, const uint2* hi, const uint32_t (*bf)[2]) {
        #pragma unroll
        for (int mi = 0; mi < 4; mi++)
            #pragma unroll
            for (int ni = 0; ni < 4; ni++) {
                asm volatile(
                    "mma.sync.aligned.m16n8k16.row.col.f32.f16.f16.f32 "
                    "{%0,%1,%2,%3}, {%4,%5,%6,%7}, {%8,%9}, {%0,%1,%2,%3};"
                    : "+f"(acc[mi][ni][0]), "+f"(acc[mi][ni][1]),
                      "+f"(acc[mi][ni][2]), "+f"(acc[mi][ni][3])
                    : "r"(lo[mi].x), "r"(hi[mi].x), "r"(lo[mi].y), "r"(hi[mi].y),
                      "r"(bf[ni][0]), "r"(bf[ni][1]));
            }
    };

    // boot: group0 = full B(0) + A(0); group1 = A(1)
    #pragma unroll
    for (int k = 0; k < 3; k++) stageBslice(0, k);
    stageA(0);
    CP_COMMIT();
    stageA(1);
    CP_COMMIT();
    CP_WAIT1();                       // A(0), B(0) resident
    __syncthreads();                  // halo zeros + stage visibility

    // prefetched ks0 fragments for chunk 0
    uint2 pAlo[4], pAhi[4];
    uint32_t pB[4][2];
    loadA(aptr(0), 0, pAlo, pAhi);
    loadB(bptr(0), 0, pB);

    for (int ch = 0; ch < 72; ch++) {
        const int cg = ch / 9, tap = ch - cg * 9;

        if (ch + 2 < 72) stageA(ch + 2);
        if (tap >= 1 && tap <= 3 && cg + 1 < 8) stageBslice(cg + 1, tap - 1);
        CP_COMMIT();

        // ks1 fragments of current chunk (hidden under ks0 MMAs)
        uint2 a1lo[4], a1hi[4];
        uint32_t b1[4][2];
        const __half2* A  = aptr(ch);
        const __half2* Bc = bptr(ch);
        loadA(A, 1, a1lo, a1hi);
        loadB(Bc, 1, b1);

        mmas(pAlo, pAhi, pB);                       // ks0 (prefetched regs)

        CP_WAIT1();                                 // A(ch+1) + B resident
        __syncthreads();                            // staging overwrite fence

        if (ch + 1 < 72) {                          // prefetch next chunk ks0
            loadA(aptr(ch + 1), 0, pAlo, pAhi);
            loadB(bptr(ch + 1), 0, pB);
        }
        mmas(a1lo, a1hi, b1);                       // ks1 (hides prefetch LDS)
    }

    // epilogue: bias + float2 stores
    const float* abp = g_aggb + b * OO;
    #pragma unroll
    for (int mi = 0; mi < 4; mi++) {
        const int o1 = o0 + wo * 64 + mi * 16 + gid;
        const float bv1 = abp[o1], bv2 = abp[o1 + 8];
        float* p1 = out + (((size_t)b * OO + o1) * HH + r0 + pr) * WW + ph * 32 + 2 * kq;
        float* p2 = p1 + (size_t)8 * HH * WW;
        #pragma unroll
        for (int ni = 0; ni < 4; ni++) {
            *(float2*)(p1 + ni * 8) = make_float2(acc[mi][ni][0] + bv1, acc[mi][ni][1] + bv1);
            *(float2*)(p2 + ni * 8) = make_float2(acc[mi][ni][2] + bv2, acc[mi][ni][3] + bv2);
        }
    }
}

// ---------------------------------------------------------------------------
extern "C" void kernel_launch(void* const* d_in, const int* in_sizes, int n_in,
                              void* d_out, int out_size) {
    const float* x      = (const float*)d_in[0];
    const float* w_fc1  = (const float*)d_in[1];
    const float* w_fc2  = (const float*)d_in[2];
    const float* b_fc2  = (const float*)d_in[3];
    const float* weight = (const float*)d_in[4];
    const float* bias   = (const float*)d_in[5];
    float* out = (float*)d_out;

    cudaFuncSetAttribute(conv_mma_kernel,
                         cudaFuncAttributeMaxDynamicSharedMemorySize, SMEM_TOTAL);

    pool_kernel<<<BB * C2, 256>>>(x);
    att_kernel<<<BB, 128>>>(w_fc1, w_fc2, b_fc2, bias);
    aggw_kernel<<<OO, 128>>>(weight);
    conv_mma_kernel<<<dim3(BB, OO / 128, HH / 4), 512, SMEM_TOTAL>>>(out);
}

// round 16
// speedup vs baseline: 1.1717x; 1.1717x over previous
#include <cuda_runtime.h>
#include <cuda_fp16.h>
#include <cstdint>

// Problem constants
#define BB   16
#define CC   256
#define HH   64
#define WW   64
#define KK   4
#define OO   256
#define HID  65
#define TEMP 34.0f
#define C2   128                        // channel pairs

// Conv tiling: CTA 128(o) x 256(px), 512 thr = 16 warps of 64x32.
// K chunk = 32 ch = 2 x k16 MMA steps.  fp16 data, fp32 accumulate.
#define AST2  24                        // A smem row stride (half2 units, 96 B)
#define SA_SZ (128 * AST2 * 4)          // 12288 B per A stage
#define BROW2 72                        // B row stride (half2)
#define BCH2  440                       // B c2-row stride (half2) = 6*72+8
#define SB_SZ (16 * BCH2 * 4)           // 28160 B per B stage (16 c2-rows)
#define SB_OFF (4 * SA_SZ)              // 49152
#define SMEM_TOTAL (SB_OFF + 2 * SB_SZ) // 105472 (103 KB)

// Scratch
__device__ float  g_pooled[BB * CC];
__device__ float  g_att[BB * KK];
__device__ float  g_aggb[BB * OO];
__device__ __half2 g_wh[(size_t)BB * 9 * OO * C2];       // [b][tap][o][c2'], perm, fp16
__device__ __half2 g_xh[(size_t)BB * C2 * HH * WW];      // [b][c2][p], (even,odd) ch

__device__ __forceinline__ uint32_t smem_u32(const void* p) {
    uint32_t a;
    asm("{ .reg .u64 t; cvta.to.shared.u64 t, %1; cvt.u32.u64 %0, t; }" : "=r"(a) : "l"(p));
    return a;
}
#define CP16(dst, src) \
    asm volatile("cp.async.cg.shared.global [%0], [%1], 16;" :: "r"(dst), "l"(src) : "memory")
#define CP16Z(dst, src, sz) \
    asm volatile("cp.async.cg.shared.global [%0], [%1], 16, %2;" :: "r"(dst), "l"(src), "r"(sz) : "memory")
#define CP_COMMIT() asm volatile("cp.async.commit_group;" ::: "memory")
#define CP_WAIT1()  asm volatile("cp.async.wait_group 1;" ::: "memory")

// ---------------------------------------------------------------------------
// K1: global average pool (fp32) + fp16 channel-pair-interleaved copy of x.
// ---------------------------------------------------------------------------
__global__ void pool_kernel(const float* __restrict__ x) {
    int blk = blockIdx.x;
    int b = blk >> 7, c2 = blk & 127;
    const float4* p0 = reinterpret_cast<const float4*>(x + ((size_t)(b * CC + 2 * c2)) * (HH * WW));
    const float4* p1 = reinterpret_cast<const float4*>(x + ((size_t)(b * CC + 2 * c2 + 1)) * (HH * WW));
    uint4* xo = reinterpret_cast<uint4*>(g_xh + ((size_t)(b * C2 + c2)) * (HH * WW));
    float sa = 0.f, sb = 0.f;
    for (int i = threadIdx.x; i < HH * WW / 4; i += blockDim.x) {
        float4 va = p0[i], vb = p1[i];
        sa += (va.x + va.y) + (va.z + va.w);
        sb += (vb.x + vb.y) + (vb.z + vb.w);
        __half2 h0 = __halves2half2(__float2half_rn(va.x), __float2half_rn(vb.x));
        __half2 h1 = __halves2half2(__float2half_rn(va.y), __float2half_rn(vb.y));
        __half2 h2 = __halves2half2(__float2half_rn(va.z), __float2half_rn(vb.z));
        __half2 h3 = __halves2half2(__float2half_rn(va.w), __float2half_rn(vb.w));
        uint4 o;
        o.x = *(uint32_t*)&h0; o.y = *(uint32_t*)&h1;
        o.z = *(uint32_t*)&h2; o.w = *(uint32_t*)&h3;
        xo[i] = o;
    }
    #pragma unroll
    for (int off = 16; off > 0; off >>= 1) {
        sa += __shfl_down_sync(0xffffffffu, sa, off);
        sb += __shfl_down_sync(0xffffffffu, sb, off);
    }
    __shared__ float wsa[8], wsb[8];
    int lane = threadIdx.x & 31, wid = threadIdx.x >> 5;
    if (lane == 0) { wsa[wid] = sa; wsb[wid] = sb; }
    __syncthreads();
    if (threadIdx.x == 0) {
        float ta = 0.f, tb = 0.f;
        int nw = blockDim.x >> 5;
        for (int i = 0; i < nw; i++) { ta += wsa[i]; tb += wsb[i]; }
        g_pooled[b * CC + 2 * c2]     = ta * (1.0f / (HH * WW));
        g_pooled[b * CC + 2 * c2 + 1] = tb * (1.0f / (HH * WW));
    }
}

// ---------------------------------------------------------------------------
// K2: attention MLP + softmax + aggregated bias
// ---------------------------------------------------------------------------
__global__ void att_kernel(const float* __restrict__ w_fc1,
                           const float* __restrict__ w_fc2,
                           const float* __restrict__ b_fc2,
                           const float* __restrict__ bias) {
    int b = blockIdx.x;
    __shared__ float sp[CC];
    __shared__ float sh[HID];
    __shared__ float satt[KK];
    for (int i = threadIdx.x; i < CC; i += blockDim.x) sp[i] = g_pooled[b * CC + i];
    __syncthreads();
    if (threadIdx.x < HID) {
        float a = 0.f;
        const float* wr = w_fc1 + threadIdx.x * CC;
        for (int j = 0; j < CC; j++) a += sp[j] * wr[j];
        sh[threadIdx.x] = fmaxf(a, 0.f);
    }
    __syncthreads();
    if (threadIdx.x == 0) {
        float lg[KK];
        float m = -1e30f;
        for (int k = 0; k < KK; k++) {
            float a = b_fc2[k];
            for (int j = 0; j < HID; j++) a += sh[j] * w_fc2[k * HID + j];
            a *= (1.0f / TEMP);
            lg[k] = a;
            m = fmaxf(m, a);
        }
        float den = 0.f;
        for (int k = 0; k < KK; k++) { lg[k] = expf(lg[k] - m); den += lg[k]; }
        float inv = 1.0f / den;
        for (int k = 0; k < KK; k++) satt[k] = lg[k] * inv;
    }
    __syncthreads();
    if (threadIdx.x < KK) g_att[b * KK + threadIdx.x] = satt[threadIdx.x];
    for (int o = threadIdx.x; o < OO; o += blockDim.x) {
        float a = 0.f;
        #pragma unroll
        for (int k = 0; k < KK; k++) a += satt[k] * bias[k * OO + o];
        g_aggb[b * OO + o] = a;
    }
}

// ---------------------------------------------------------------------------
// K3: aggregate weights -> g_wh[b][tap][o][c2'] (fp16 half2, perm within
// 8-half2 k16-blocks: j<4 -> 2j, j>=4 -> 2(j-4)+1).  weight read ONCE.
// ---------------------------------------------------------------------------
__global__ void aggw_kernel(const float* __restrict__ weight) {
    int o = blockIdx.x;
    int c2 = threadIdx.x;              // 0..127
    __shared__ float satt[BB * KK];
    if (c2 < BB * KK) satt[c2] = g_att[c2];
    __syncthreads();
    float wv0[KK][9], wv1[KK][9];
    #pragma unroll
    for (int k = 0; k < KK; k++) {
        const float* wp = weight + (((size_t)k * OO + o) * CC + 2 * c2) * 9;
        #pragma unroll
        for (int t = 0; t < 9; t++) { wv0[k][t] = wp[t]; wv1[k][t] = wp[9 + t]; }
    }
    int j = c2 & 7;
    int cpos = (c2 & ~7) | ((j < 4) ? (2 * j) : (2 * (j - 4) + 1));
    for (int b = 0; b < BB; b++) {
        float a0 = satt[b * KK + 0], a1 = satt[b * KK + 1];
        float a2 = satt[b * KK + 2], a3 = satt[b * KK + 3];
        #pragma unroll
        for (int t = 0; t < 9; t++) {
            float v0 = a0 * wv0[0][t] + a1 * wv0[1][t] + a2 * wv0[2][t] + a3 * wv0[3][t];
            float v1 = a0 * wv1[0][t] + a1 * wv1[1][t] + a2 * wv1[2][t] + a3 * wv1[3][t];
            g_wh[(((size_t)b * 9 + t) * OO + o) * C2 + cpos] =
                __halves2half2(__float2half_rn(v0), __float2half_rn(v1));
        }
    }
}

// ---------------------------------------------------------------------------
// K4: fp16 m16n8k16 mma.sync implicit-GEMM conv, register-pipelined mainloop
// with COMPILE-TIME tap addressing (outer cg loop, inner 9-tap full unroll).
// Next-chunk ks0 fragments prefetched into regs after the barrier; all tap
// offsets fold to immediates so the R9 ALU overhead disappears.
// ---------------------------------------------------------------------------
__global__ void __launch_bounds__(512, 1)
conv_mma_kernel(float* __restrict__ out) {
    extern __shared__ char smem[];
    __half2* smh = (__half2*)smem;
    const uint32_t sbu = smem_u32(smem);
    const int tid  = threadIdx.x;
    const int lane = tid & 31;
    const int w    = tid >> 5;
    const int wo   = w >> 3;
    const int wp   = w & 7;
    const int pr   = wp >> 1;
    const int ph   = wp & 1;
    const int gid  = lane >> 2;
    const int kq   = lane & 3;
    const int b  = blockIdx.x;
    const int o0 = blockIdx.y * 128;
    const int r0 = blockIdx.z * 4;

    const __half2* xb = g_xh + (size_t)b * C2 * HH * WW;
    const __half2* wb = g_wh + (size_t)b * 9 * OO * C2;

    // zero halo half2 cells (pos 3 = x col -1, pos 68 = x col 64), both B stages
    for (int i = tid; i < 2 * 16 * 6 * 2; i += 512) {
        int st  = i / 192;
        int rem = i - st * 192;
        int c = rem / 12, r2 = rem - c * 12;
        int rr = r2 >> 1, h = r2 & 1;
        smh[(SB_OFF / 4) + st * (SB_SZ / 4) + c * BCH2 + rr * BROW2 + (h ? 68 : 3)] =
            __halves2half2(__float2half_rn(0.f), __float2half_rn(0.f));
    }

    float acc[4][4][4];
    #pragma unroll
    for (int mi = 0; mi < 4; mi++)
        #pragma unroll
        for (int ni = 0; ni < 4; ni++)
            #pragma unroll
            for (int q = 0; q < 4; q++) acc[mi][ni][q] = 0.f;

    // per-thread constant offsets (half2 units)
    const int aoff = (wo * 64 + gid) * AST2 + kq * 2;      // A fragment base
    const int boff = (1 + pr) * BROW2 + 4 + ph * 32 + gid; // B base (tap 4 center)
    const int st_arow = tid >> 2, st_aseg = tid & 3;       // A staging
    const int st_c = tid / 96,  st_rem = tid - (tid / 96) * 96;
    const int st_brow = st_rem >> 4, st_bseg = st_rem & 15;

    // ---- staging helpers (src indices compile-time per unrolled tap)
    auto stageA = [&](int ch, int tap2, int cg2) {
        uint32_t dst0 = sbu + (uint32_t)((ch & 3) * SA_SZ);
        const __half2* src0 = wb + ((size_t)tap2 * OO + o0) * C2 + cg2 * 16;
        CP16(dst0 + (uint32_t)((st_arow * AST2 + st_aseg * 4) * 4),
             src0 + (size_t)st_arow * C2 + st_aseg * 4);
    };
    auto stageBslice = [&](int cgn, int k) {
        int c = st_c + (k >> 1) * 6;                 // k in 0..2 -> c offset 0/0/6? (see below)
        (void)c;
    };
    (void)stageBslice;
    // B staging: 3 slices of 512 x 16B each; slice k covers j = tid + k*512
    auto stageB = [&](int cgn, int k) {
        int j = tid + k * 512;
        int c = j / 96, rem = j - c * 96;
        int row = rem >> 4, seg = rem & 15;
        int rr = r0 - 1 + row;
        bool ok = (unsigned)rr < (unsigned)HH;
        const __half2* src = xb + ((size_t)(cgn * 16 + c) * HH + (ok ? rr : 0)) * WW + seg * 4;
        uint32_t dst = sbu + SB_OFF + (uint32_t)((cgn & 1) * SB_SZ)
                     + (uint32_t)((c * BCH2 + row * BROW2 + 4 + seg * 4) * 4);
        CP16Z(dst, src, ok ? 16 : 0);
    };

    auto mmas = [&](const uint2* lo, const uint2* hi, const uint32_t (*bf)[2]) {
        #pragma unroll
        for (int mi = 0; mi < 4; mi++)
            #pragma unroll
            for (int ni = 0; ni < 4; ni++) {
                asm volatile(
                    "mma.sync.aligned.m16n8k16.row.col.f32.f16.f16.f32 "
                    "{%0,%1,%2,%3}, {%4,%5,%6,%7}, {%8,%9}, {%0,%1,%2,%3};"
                    : "+f"(acc[mi][ni][0]), "+f"(acc[mi][ni][1]),
                      "+f"(acc[mi][ni][2]), "+f"(acc[mi][ni][3])
                    : "r"(lo[mi].x), "r"(hi[mi].x), "r"(lo[mi].y), "r"(hi[mi].y),
                      "r"(bf[ni][0]), "r"(bf[ni][1]));
            }
    };

    #define LOADA_F(Abase, ksc, lo, hi)                                   \
        _Pragma("unroll")                                                 \
        for (int mi = 0; mi < 4; mi++) {                                  \
            const __half2* _p = (Abase) + mi * 16 * AST2 + (ksc) * 8;     \
            lo[mi] = *(const uint2*)_p;                                   \
            hi[mi] = *(const uint2*)(_p + 8 * AST2);                      \
        }
    #define LOADB_F(Bbase, ksc, bf)                                       \
        {                                                                 \
            const __half2* _Bk = (Bbase) + ((ksc) * 8 + kq) * BCH2;       \
            _Pragma("unroll")                                             \
            for (int ni = 0; ni < 4; ni++) {                              \
                bf[ni][0] = *(const uint32_t*)(_Bk + ni * 8);             \
                bf[ni][1] = *(const uint32_t*)(_Bk + 4 * BCH2 + ni * 8);  \
            }                                                             \
        }

    // boot: group0 = full B(0) + A(0); group1 = A(1)
    #pragma unroll
    for (int k = 0; k < 3; k++) stageB(0, k);
    stageA(0, 0, 0);
    CP_COMMIT();
    stageA(1, 1, 0);
    CP_COMMIT();
    CP_WAIT1();
    __syncthreads();

    // prefetched ks0 fragments for chunk 0 (tap 0: dy=-1, dx=-1)
    uint2 pAlo[4], pAhi[4];
    uint32_t pB[4][2];
    {
        const __half2* A0 = smh + aoff;
        const __half2* B0 = smh + (SB_OFF / 4) + boff - BROW2 - 1;
        LOADA_F(A0, 0, pAlo, pAhi);
        LOADB_F(B0, 0, pB);
    }

    for (int cg = 0; cg < 8; cg++) {
        const __half2* Bst  = smh + (SB_OFF / 4) + (cg & 1) * (SB_SZ / 4) + boff;
        const __half2* BstN = smh + (SB_OFF / 4) + ((cg + 1) & 1) * (SB_SZ / 4) + boff;
        #pragma unroll
        for (int tap = 0; tap < 9; tap++) {
            const int ch = cg * 9 + tap;
            const int dy = tap / 3 - 1, dx = tap % 3 - 1;          // compile-time

            // stage ahead: A(ch+2) and one B slice for cg+1 during taps 1..3
            if (ch + 2 < 72) {
                if (tap <= 6) stageA(ch + 2, tap + 2, cg);
                else          stageA(ch + 2, tap - 7, cg + 1);
            }
            if (tap >= 1 && tap <= 3 && cg + 1 < 8) stageB(cg + 1, tap - 1);
            CP_COMMIT();

            // current-chunk ks1 fragments (hide under ks0 MMAs)
            const __half2* A  = smh + (ch & 3) * (SA_SZ / 4) + aoff;
            const __half2* Bc = Bst + (dy * BROW2 + dx);           // immediate
            uint2 a1lo[4], a1hi[4];
            uint32_t b1[4][2];
            LOADA_F(A, 1, a1lo, a1hi);
            LOADB_F(Bc, 1, b1);

            mmas(pAlo, pAhi, pB);                                  // ks0

            CP_WAIT1();
            __syncthreads();

            // prefetch next chunk's ks0 fragments (compile-time next tap)
            if (ch + 1 < 72) {
                const __half2* An = smh + ((ch + 1) & 3) * (SA_SZ / 4) + aoff;
                const __half2* Bn;
                if (tap < 8) {
                    const int dy2 = (tap + 1) / 3 - 1, dx2 = (tap + 1) % 3 - 1;
                    Bn = Bst + (dy2 * BROW2 + dx2);
                } else {
                    Bn = BstN - BROW2 - 1;                         // next cg, tap 0
                }
                LOADA_F(An, 0, pAlo, pAhi);
                LOADB_F(Bn, 0, pB);
            }

            mmas(a1lo, a1hi, b1);                                  // ks1
        }
    }

    // epilogue: bias + float2 stores
    const float* abp = g_aggb + b * OO;
    #pragma unroll
    for (int mi = 0; mi < 4; mi++) {
        const int o1 = o0 + wo * 64 + mi * 16 + gid;
        const float bv1 = abp[o1], bv2 = abp[o1 + 8];
        float* p1 = out + (((size_t)b * OO + o1) * HH + r0 + pr) * WW + ph * 32 + 2 * kq;
        float* p2 = p1 + (size_t)8 * HH * WW;
        #pragma unroll
        for (int ni = 0; ni < 4; ni++) {
            *(float2*)(p1 + ni * 8) = make_float2(acc[mi][ni][0] + bv1, acc[mi][ni][1] + bv1);
            *(float2*)(p2 + ni * 8) = make_float2(acc[mi][ni][2] + bv2, acc[mi][ni][3] + bv2);
        }
    }
    #undef LOADA_F
    #undef LOADB_F
}

// ---------------------------------------------------------------------------
extern "C" void kernel_launch(void* const* d_in, const int* in_sizes, int n_in,
                              void* d_out, int out_size) {
    const float* x      = (const float*)d_in[0];
    const float* w_fc1  = (const float*)d_in[1];
    const float* w_fc2  = (const float*)d_in[2];
    const float* b_fc2  = (const float*)d_in[3];
    const float* weight = (const float*)d_in[4];
    const float* bias   = (const float*)d_in[5];
    float* out = (float*)d_out;

    cudaFuncSetAttribute(conv_mma_kernel,
                         cudaFuncAttributeMaxDynamicSharedMemorySize, SMEM_TOTAL);

    pool_kernel<<<BB * C2, 256>>>(x);
    att_kernel<<<BB, 128>>>(w_fc1, w_fc2, b_fc2, bias);
    aggw_kernel<<<OO, 128>>>(weight);
    conv_mma_kernel<<<dim3(BB, OO / 128, HH / 4), 512, SMEM_TOTAL>>>(out);
}